// round 5
// baseline (speedup 1.0000x reference)
#include <cuda_runtime.h>

#define BATCH 8
#define HH 512
#define WW 512
#define W2 (WW / 2)
#define PLANE (HH * WW)
#define NP (BATCH * PLANE)
#define RAD 15
#define INV_K2 (1.0f / 961.0f)
#define EPSV 1e-6f
#define SEG 32        // rows per vertical segment (k_v2)
#define SEGV 32       // rows per vertical segment (k_vh)
#define SPAD 544
#define PADI(i) ((i) + ((i) >> 4))

// -------- scratch (device globals) --------
// stage-1 quantities: 0=I, 1=I*I, 2..4=p_c, 5..7=I*p_c
__device__ float g_gray[NP];      // 8 MB
__device__ float g_hsum[8][NP];   // 64 MB
__device__ float g_hsum2[6][NP];  // 48 MB

__device__ __forceinline__ float iscan(float v, int lane) {
#pragma unroll
    for (int o = 1; o < 32; o <<= 1) {
        float n = __shfl_up_sync(0xffffffffu, v, o);
        if (lane >= o) v += n;
    }
    return v;
}

// ============================================================================
// K1: horizontal pass, chunk-local scan, single reusable p-staging buffer
// with register prefetch of the next channel. 1 warp/row, 4 rows/block.
// ============================================================================
__global__ __launch_bounds__(128) void k_h1(const float* __restrict__ guide,
                                            const float* __restrict__ input) {
    const int warp = threadIdx.x >> 5;
    const int lane = threadIdx.x & 31;
    const int grow = blockIdx.x * 4 + warp;
    const int b = grow >> 9;
    const int r = grow & 511;

    const float* gR = guide + ((size_t)(b * 3 + 0) * HH + r) * WW;
    const float* gG = guide + ((size_t)(b * 3 + 1) * HH + r) * WW;
    const float* gB = guide + ((size_t)(b * 3 + 2) * HH + r) * WW;
    const float* p0 = input + ((size_t)(b * 3 + 0) * HH + r) * WW;
    const float* p1 = input + ((size_t)(b * 3 + 1) * HH + r) * WW;
    const float* p2 = input + ((size_t)(b * 3 + 2) * HH + r) * WW;

    __shared__ float sg[4][SPAD];    // gray
    __shared__ float sq[4][SPAD];    // reusable p staging
    __shared__ float sp[4][SPAD];    // prefix buffer
    float* g    = sg[warp];
    float* qbuf = sq[warp];
    float* pref = sp[warp];

    const size_t rowOff = (size_t)grow * WW;

    // stage gray + p0 (coalesced), write gray plane
#pragma unroll
    for (int i = 0; i < 16; i++) {
        int c = i * 32 + lane;
        float gr = 0.299f * gR[c] + 0.587f * gG[c] + 0.114f * gB[c];
        g[PADI(c)] = gr;
        g_gray[rowOff + c] = gr;
        qbuf[PADI(c)] = p0[c];
    }
    __syncwarp();

    const int cb = lane * 16;
    float gv[16], pv[16], nreg[16], lp[16];

    auto scan_store = [&](float* __restrict__ outp) {
        float tot = lp[15];
        float ex = iscan(tot, lane) - tot;
#pragma unroll
        for (int k = 0; k < 16; k++) pref[PADI(cb + k)] = ex + lp[k];
        __syncwarp();
#pragma unroll
        for (int i = 0; i < 16; i++) {
            int x = i * 32 + lane;
            int hx = (x + RAD > WW - 1) ? (WW - 1) : (x + RAD);
            float hi = pref[PADI(hx)];
            float lo = (x >= RAD + 1) ? pref[PADI(x - RAD - 1)] : 0.f;
            outp[x] = hi - lo;
        }
        __syncwarp();
    };

    // I and I*I
    { float a = 0.f;
#pragma unroll
      for (int k = 0; k < 16; k++) { gv[k] = g[PADI(cb + k)]; a += gv[k]; lp[k] = a; } }
    scan_store(g_hsum[0] + rowOff);
    { float a = 0.f;
#pragma unroll
      for (int k = 0; k < 16; k++) { a += gv[k] * gv[k]; lp[k] = a; } }
    scan_store(g_hsum[1] + rowOff);

    // ---- p0 (prefetch p1 into registers, overlapped with the two scans) ----
#pragma unroll
    for (int k = 0; k < 16; k++) pv[k] = qbuf[PADI(cb + k)];
#pragma unroll
    for (int i = 0; i < 16; i++) nreg[i] = p1[i * 32 + lane];
    { float a = 0.f;
#pragma unroll
      for (int k = 0; k < 16; k++) { a += pv[k]; lp[k] = a; } }
    scan_store(g_hsum[2] + rowOff);
    { float a = 0.f;
#pragma unroll
      for (int k = 0; k < 16; k++) { a += gv[k] * pv[k]; lp[k] = a; } }
    scan_store(g_hsum[5] + rowOff);

    // swap in p1, prefetch p2
    __syncwarp();
#pragma unroll
    for (int i = 0; i < 16; i++) qbuf[PADI(i * 32 + lane)] = nreg[i];
    __syncwarp();
#pragma unroll
    for (int k = 0; k < 16; k++) pv[k] = qbuf[PADI(cb + k)];
#pragma unroll
    for (int i = 0; i < 16; i++) nreg[i] = p2[i * 32 + lane];
    { float a = 0.f;
#pragma unroll
      for (int k = 0; k < 16; k++) { a += pv[k]; lp[k] = a; } }
    scan_store(g_hsum[3] + rowOff);
    { float a = 0.f;
#pragma unroll
      for (int k = 0; k < 16; k++) { a += gv[k] * pv[k]; lp[k] = a; } }
    scan_store(g_hsum[6] + rowOff);

    // swap in p2
    __syncwarp();
#pragma unroll
    for (int i = 0; i < 16; i++) qbuf[PADI(i * 32 + lane)] = nreg[i];
    __syncwarp();
#pragma unroll
    for (int k = 0; k < 16; k++) pv[k] = qbuf[PADI(cb + k)];
    { float a = 0.f;
#pragma unroll
      for (int k = 0; k < 16; k++) { a += pv[k]; lp[k] = a; } }
    scan_store(g_hsum[4] + rowOff);
    { float a = 0.f;
#pragma unroll
      for (int k = 0; k < 16; k++) { a += gv[k] * pv[k]; lp[k] = a; } }
    scan_store(g_hsum[7] + rowOff);
}

// ============================================================================
// K2 (fused vertical+horizontal on a,b): 512 threads = full row (1 col/thr),
// SEGV=32 rows/block. 2 barriers/row, double-buffered smem, slide prefetch.
// grid (HH/SEGV, BATCH) = (16, 8)
// ============================================================================
__global__ __launch_bounds__(512) void k_vh() {
    const int tid  = threadIdx.x;       // column x
    const int warp = tid >> 5;          // 0..15
    const int lane = tid & 31;
    const int r0 = blockIdx.x * SEGV;
    const int b  = blockIdx.y;
    const size_t base = (size_t)b * PLANE + tid;

    __shared__ float s_pref[2][6][WW];   // 24 KB
    __shared__ float s_wtot[2][6][16];

    float s[8];
#pragma unroll
    for (int q = 0; q < 8; q++) s[q] = 0.f;

    const int jstart = (r0 - RAD < 0) ? 0 : (r0 - RAD);
#pragma unroll 4
    for (int j = jstart; j <= r0 + RAD; j++) {
        const size_t off = base + (size_t)j * WW;
#pragma unroll
        for (int q = 0; q < 8; q++) s[q] += g_hsum[q][off];
    }

    for (int i = 0; i < SEGV; i++) {
        const int row = r0 + i;
        const size_t off = base + (size_t)row * WW;
        const int bu = i & 1;

        // ---- prefetch next slide loads ----
        const int lead  = row + RAD + 1;
        const int trail = row - RAD;
        const bool hl = lead < HH;
        const bool ht = trail >= 0;
        float ldv[8], trv[8];
        if (hl) {
            const size_t lo = base + (size_t)lead * WW;
#pragma unroll
            for (int q = 0; q < 8; q++) ldv[q] = g_hsum[q][lo];
        }
        if (ht) {
            const size_t to = base + (size_t)trail * WW;
#pragma unroll
            for (int q = 0; q < 8; q++) trv[q] = g_hsum[q][to];
        }

        // ---- a,b for this row (this column) ----
        float ab[6];
        {
            float mI = s[0] * INV_K2;
            float cI = s[1] * INV_K2;
            float iv = 1.f / (cI - mI * mI + EPSV);
#pragma unroll
            for (int c = 0; c < 3; c++) {
                float mp  = s[2 + c] * INV_K2;
                float cIp = s[5 + c] * INV_K2;
                float a   = (cIp - mI * mp) * iv;
                ab[c]     = a;
                ab[3 + c] = mp - a * mI;
            }
        }

        // ---- block prefix scan over 512 cols, 6 quantities (2 barriers) ----
        float wv[6];
#pragma unroll
        for (int q = 0; q < 6; q++) {
            wv[q] = iscan(ab[q], lane);
            if (lane == 31) s_wtot[bu][q][warp] = wv[q];
        }
        __syncthreads();
#pragma unroll
        for (int q = 0; q < 6; q++) {
            float carry = 0.f;
#pragma unroll
            for (int w = 0; w < 15; w++) if (w < warp) carry += s_wtot[bu][q][w];
            s_pref[bu][q][tid] = carry + wv[q];
        }
        __syncthreads();

        // ---- horizontal box sums -> g_hsum2 ----
        const int hx = (tid + RAD > WW - 1) ? (WW - 1) : (tid + RAD);
        const bool hasLo = tid >= RAD + 1;
        const int lx = hasLo ? (tid - RAD - 1) : 0;
#pragma unroll
        for (int q = 0; q < 6; q++) {
            float hi = s_pref[bu][q][hx];
            float lo = hasLo ? s_pref[bu][q][lx] : 0.f;
            g_hsum2[q][off] = hi - lo;
        }

        // ---- apply slide ----
        if (hl) {
#pragma unroll
            for (int q = 0; q < 8; q++) s[q] += ldv[q];
        }
        if (ht) {
#pragma unroll
            for (int q = 0; q < 8; q++) s[q] -= trv[q];
        }
    }
}

// ============================================================================
// K3: vertical running sums on hsum2 (float2/thread, 256 thr = full row),
// per channel, fused output. grid (1, HH/SEG, BATCH*3) = (1, 16, 24)
// ============================================================================
__global__ __launch_bounds__(256) void k_v2(float* __restrict__ out) {
    const int t  = threadIdx.x;                 // float2 column index
    const int zc = blockIdx.z;
    const int b  = zc / 3;
    const int c  = zc - b * 3;
    const int r0 = blockIdx.y * SEG;
    const size_t base = (size_t)b * (PLANE / 2) + t;

    const float2* __restrict__ pa = (const float2*)g_hsum2[c];
    const float2* __restrict__ pb = (const float2*)g_hsum2[3 + c];
    const float2* __restrict__ pg = (const float2*)g_gray;
    float2* __restrict__ po = (float2*)(out + (size_t)zc * PLANE);

    float2 sa = make_float2(0.f, 0.f);
    float2 sb = make_float2(0.f, 0.f);

    const int jstart = (r0 - RAD < 0) ? 0 : (r0 - RAD);
#pragma unroll 4
    for (int j = jstart; j <= r0 + RAD; j++) {
        const size_t off = base + (size_t)j * W2;
        float2 va = pa[off], vb = pb[off];
        sa.x += va.x; sa.y += va.y;
        sb.x += vb.x; sb.y += vb.y;
    }

#pragma unroll 4
    for (int i = 0; i < SEG; i++) {
        const int row = r0 + i;
        const size_t off = base + (size_t)row * W2;

        const int lead  = row + RAD + 1;
        const int trail = row - RAD;
        const bool hl = lead < HH;
        const bool ht = trail >= 0;
        float2 la, lb, ta, tb;
        if (hl) {
            const size_t lo = base + (size_t)lead * W2;
            la = pa[lo]; lb = pb[lo];
        }
        if (ht) {
            const size_t to = base + (size_t)trail * W2;
            ta = pa[to]; tb = pb[to];
        }

        const float2 gr = pg[off];
        float2 o;
        o.x = (sa.x * INV_K2) * gr.x + sb.x * INV_K2;
        o.y = (sa.y * INV_K2) * gr.y + sb.y * INV_K2;
        po[(size_t)row * W2 + t] = o;

        if (hl) {
            sa.x += la.x; sa.y += la.y;
            sb.x += lb.x; sb.y += lb.y;
        }
        if (ht) {
            sa.x -= ta.x; sa.y -= ta.y;
            sb.x -= tb.x; sb.y -= tb.y;
        }
    }
}

// ============================================================================
extern "C" void kernel_launch(void* const* d_in, const int* in_sizes, int n_in,
                              void* d_out, int out_size) {
    const float* guide = (const float*)d_in[0];
    const float* input = (const float*)d_in[1];
    float* out = (float*)d_out;

    k_h1<<<BATCH * HH / 4, 128>>>(guide, input);
    k_vh<<<dim3(HH / SEGV, BATCH), 512>>>();
    k_v2<<<dim3(1, HH / SEG, BATCH * 3), 256>>>(out);
}

// round 6
// speedup vs baseline: 1.7525x; 1.7525x over previous
#include <cuda_runtime.h>

#define BATCH 8
#define HH 512
#define WW 512
#define W2 (WW / 2)
#define W4 (WW / 4)
#define PLANE (HH * WW)
#define NP (BATCH * PLANE)
#define RAD 15
#define INV_K2 (1.0f / 961.0f)
#define EPSV 1e-6f
#define SEG 16        // rows per vertical segment (k_v2)  [R4 config]
#define SEGV 16       // rows per vertical segment (k_vh)  [R4 config]
#define SPAD 544
#define PADI(i) ((i) + ((i) >> 4))

// -------- scratch (device globals) --------
// stage-1 quantities: 0=I, 1=I*I, 2..4=p_c, 5..7=I*p_c
__device__ float g_gray[NP];      // 8 MB
__device__ float g_hsum[8][NP];   // 64 MB
__device__ float g_hsum2[6][NP];  // 48 MB

__device__ __forceinline__ float iscan(float v, int lane) {
#pragma unroll
    for (int o = 1; o < 32; o <<= 1) {
        float n = __shfl_up_sync(0xffffffffu, v, o);
        if (lane >= o) v += n;
    }
    return v;
}

// ============================================================================
// K1: horizontal pass, chunk-local scan, NO smem staging.
// Each thread owns 16 contiguous columns, loaded via 4x float4 straight from
// global (L1 makes the strided pattern cheap). smem = prefix buffer only.
// 1 warp/row, 4 rows/block.
// ============================================================================
__global__ __launch_bounds__(128) void k_h1(const float* __restrict__ guide,
                                            const float* __restrict__ input) {
    const int warp = threadIdx.x >> 5;
    const int lane = threadIdx.x & 31;
    const int grow = blockIdx.x * 4 + warp;
    const int b = grow >> 9;
    const int r = grow & 511;

    const float* gR = guide + ((size_t)(b * 3 + 0) * HH + r) * WW;
    const float* gG = guide + ((size_t)(b * 3 + 1) * HH + r) * WW;
    const float* gB = guide + ((size_t)(b * 3 + 2) * HH + r) * WW;
    const float* p0 = input + ((size_t)(b * 3 + 0) * HH + r) * WW;
    const float* p1 = input + ((size_t)(b * 3 + 1) * HH + r) * WW;
    const float* p2 = input + ((size_t)(b * 3 + 2) * HH + r) * WW;

    __shared__ float sp[4][SPAD];    // prefix buffer (8.7 KB total)
    float* pref = sp[warp];

    const size_t rowOff = (size_t)grow * WW;
    const int cb = lane * 16;        // this thread's first column

    float gv[16], pv[16], lp[16];

    // ---- grayscale chunk, direct vector loads ----
#pragma unroll
    for (int j = 0; j < 4; j++) {
        float4 rv = ((const float4*)(gR + cb))[j];
        float4 gg = ((const float4*)(gG + cb))[j];
        float4 bv = ((const float4*)(gB + cb))[j];
        gv[4*j+0] = 0.299f * rv.x + 0.587f * gg.x + 0.114f * bv.x;
        gv[4*j+1] = 0.299f * rv.y + 0.587f * gg.y + 0.114f * bv.y;
        gv[4*j+2] = 0.299f * rv.z + 0.587f * gg.z + 0.114f * bv.z;
        gv[4*j+3] = 0.299f * rv.w + 0.587f * gg.w + 0.114f * bv.w;
    }
    // persist gray plane (vector stores)
#pragma unroll
    for (int j = 0; j < 4; j++) {
        float4 o;
        o.x = gv[4*j+0]; o.y = gv[4*j+1]; o.z = gv[4*j+2]; o.w = gv[4*j+3];
        ((float4*)(g_gray + rowOff + cb))[j] = o;
    }

    auto scan_store = [&](float* __restrict__ outp) {
        float tot = lp[15];
        float ex = iscan(tot, lane) - tot;
#pragma unroll
        for (int k = 0; k < 16; k++) pref[PADI(cb + k)] = ex + lp[k];
        __syncwarp();
#pragma unroll
        for (int i = 0; i < 16; i++) {
            int x = i * 32 + lane;
            int hx = (x + RAD > WW - 1) ? (WW - 1) : (x + RAD);
            float hi = pref[PADI(hx)];
            float lo = (x >= RAD + 1) ? pref[PADI(x - RAD - 1)] : 0.f;
            outp[x] = hi - lo;
        }
        __syncwarp();
    };

    // I
    { float a = 0.f;
#pragma unroll
      for (int k = 0; k < 16; k++) { a += gv[k]; lp[k] = a; } }
    scan_store(g_hsum[0] + rowOff);
    // I*I
    { float a = 0.f;
#pragma unroll
      for (int k = 0; k < 16; k++) { a += gv[k] * gv[k]; lp[k] = a; } }
    scan_store(g_hsum[1] + rowOff);

    const float* pc[3] = { p0, p1, p2 };
    const int qp[3] = { 2, 3, 4 };
    const int qip[3] = { 5, 6, 7 };
#pragma unroll
    for (int c = 0; c < 3; c++) {
#pragma unroll
        for (int j = 0; j < 4; j++) {
            float4 v = ((const float4*)(pc[c] + cb))[j];
            pv[4*j+0] = v.x; pv[4*j+1] = v.y; pv[4*j+2] = v.z; pv[4*j+3] = v.w;
        }
        { float a = 0.f;
#pragma unroll
          for (int k = 0; k < 16; k++) { a += pv[k]; lp[k] = a; } }
        scan_store(g_hsum[qp[c]] + rowOff);
        { float a = 0.f;
#pragma unroll
          for (int k = 0; k < 16; k++) { a += gv[k] * pv[k]; lp[k] = a; } }
        scan_store(g_hsum[qip[c]] + rowOff);
    }
}

// ============================================================================
// K2 (fused vertical+horizontal on a,b): 256 threads = full row (float2/thr),
// SEGV=16. 2 barriers/row, double-buffered smem, slide prefetch. [R4 config]
// grid (HH/SEGV, BATCH) = (32, 8) = 256 blocks
// ============================================================================
__global__ __launch_bounds__(256) void k_vh() {
    const int tid  = threadIdx.x;
    const int warp = tid >> 5;
    const int lane = tid & 31;
    const int r0 = blockIdx.x * SEGV;
    const int b  = blockIdx.y;
    const size_t base = (size_t)b * (PLANE / 2) + tid;

    __shared__ float s_pref[2][6][WW];   // 24 KB
    __shared__ float s_wtot[2][6][8];

    float2 s[8];
#pragma unroll
    for (int q = 0; q < 8; q++) { s[q].x = 0.f; s[q].y = 0.f; }

    const int jstart = (r0 - RAD < 0) ? 0 : (r0 - RAD);
#pragma unroll 4
    for (int j = jstart; j <= r0 + RAD; j++) {
        const size_t off = base + (size_t)j * W2;
#pragma unroll
        for (int q = 0; q < 8; q++) {
            float2 v = ((const float2*)g_hsum[q])[off];
            s[q].x += v.x; s[q].y += v.y;
        }
    }

    for (int i = 0; i < SEGV; i++) {
        const int row = r0 + i;
        const size_t off = base + (size_t)row * W2;
        const int bu = i & 1;

        const int lead  = row + RAD + 1;
        const int trail = row - RAD;
        const bool hl = lead < HH;
        const bool ht = trail >= 0;
        float2 ldv[8], trv[8];
        if (hl) {
            const size_t lo = base + (size_t)lead * W2;
#pragma unroll
            for (int q = 0; q < 8; q++) ldv[q] = ((const float2*)g_hsum[q])[lo];
        }
        if (ht) {
            const size_t to = base + (size_t)trail * W2;
#pragma unroll
            for (int q = 0; q < 8; q++) trv[q] = ((const float2*)g_hsum[q])[to];
        }

        float2 ab[6];
        {
            float mIx = s[0].x * INV_K2, mIy = s[0].y * INV_K2;
            float cIx = s[1].x * INV_K2, cIy = s[1].y * INV_K2;
            float ivx = 1.f / (cIx - mIx * mIx + EPSV);
            float ivy = 1.f / (cIy - mIy * mIy + EPSV);
#pragma unroll
            for (int c = 0; c < 3; c++) {
                float mpx  = s[2 + c].x * INV_K2, mpy  = s[2 + c].y * INV_K2;
                float cIpx = s[5 + c].x * INV_K2, cIpy = s[5 + c].y * INV_K2;
                float ax = (cIpx - mIx * mpx) * ivx;
                float ay = (cIpy - mIy * mpy) * ivy;
                ab[c].x = ax;                 ab[c].y = ay;
                ab[3 + c].x = mpx - ax * mIx; ab[3 + c].y = mpy - ay * mIy;
            }
        }

        float tq[6], wv[6];
#pragma unroll
        for (int q = 0; q < 6; q++) {
            tq[q] = ab[q].x + ab[q].y;
            wv[q] = iscan(tq[q], lane);
            if (lane == 31) s_wtot[bu][q][warp] = wv[q];
        }
        __syncthreads();
#pragma unroll
        for (int q = 0; q < 6; q++) {
            float carry = 0.f;
#pragma unroll
            for (int w = 0; w < 7; w++) if (w < warp) carry += s_wtot[bu][q][w];
            float ex = wv[q] - tq[q] + carry;
            float2 pr;
            pr.x = ex + ab[q].x;
            pr.y = pr.x + ab[q].y;
            ((float2*)s_pref[bu][q])[tid] = pr;
        }
        __syncthreads();

        const int x0 = 2 * tid, x1 = x0 + 1;
        const int h0 = (x0 + RAD > WW - 1) ? (WW - 1) : (x0 + RAD);
        const int h1 = (x1 + RAD > WW - 1) ? (WW - 1) : (x1 + RAD);
#pragma unroll
        for (int q = 0; q < 6; q++) {
            float lo0 = (x0 >= RAD + 1) ? s_pref[bu][q][x0 - RAD - 1] : 0.f;
            float lo1 = (x1 >= RAD + 1) ? s_pref[bu][q][x1 - RAD - 1] : 0.f;
            float2 o;
            o.x = s_pref[bu][q][h0] - lo0;
            o.y = s_pref[bu][q][h1] - lo1;
            ((float2*)g_hsum2[q])[off] = o;
        }

        if (hl) {
#pragma unroll
            for (int q = 0; q < 8; q++) { s[q].x += ldv[q].x; s[q].y += ldv[q].y; }
        }
        if (ht) {
#pragma unroll
            for (int q = 0; q < 8; q++) { s[q].x -= trv[q].x; s[q].y -= trv[q].y; }
        }
    }
}

// ============================================================================
// K3: vertical running sums on hsum2 (float4/thread), per channel, fused
// output. [R4 config] grid (1, HH/SEG, BATCH*3) = (1, 32, 24) = 768 blocks
// ============================================================================
__global__ __launch_bounds__(128) void k_v2(float* __restrict__ out) {
    const int t  = threadIdx.x;
    const int zc = blockIdx.z;
    const int b  = zc / 3;
    const int c  = zc - b * 3;
    const int r0 = blockIdx.y * SEG;
    const size_t base = (size_t)b * (PLANE / 4) + t;

    const float4* __restrict__ pa = (const float4*)g_hsum2[c];
    const float4* __restrict__ pb = (const float4*)g_hsum2[3 + c];
    const float4* __restrict__ pg = (const float4*)g_gray;
    float4* __restrict__ po = (float4*)(out + (size_t)zc * PLANE);

    float4 sa = make_float4(0.f, 0.f, 0.f, 0.f);
    float4 sb = make_float4(0.f, 0.f, 0.f, 0.f);

    const int jstart = (r0 - RAD < 0) ? 0 : (r0 - RAD);
#pragma unroll 4
    for (int j = jstart; j <= r0 + RAD; j++) {
        const size_t off = base + (size_t)j * W4;
        float4 va = pa[off], vb = pb[off];
        sa.x += va.x; sa.y += va.y; sa.z += va.z; sa.w += va.w;
        sb.x += vb.x; sb.y += vb.y; sb.z += vb.z; sb.w += vb.w;
    }

#pragma unroll 4
    for (int i = 0; i < SEG; i++) {
        const int row = r0 + i;
        const size_t off = base + (size_t)row * W4;

        const int lead  = row + RAD + 1;
        const int trail = row - RAD;
        const bool hl = lead < HH;
        const bool ht = trail >= 0;
        float4 la, lb, ta, tb;
        if (hl) {
            const size_t lo = base + (size_t)lead * W4;
            la = pa[lo]; lb = pb[lo];
        }
        if (ht) {
            const size_t to = base + (size_t)trail * W4;
            ta = pa[to]; tb = pb[to];
        }

        const float4 gr = pg[off];
        float4 o;
        o.x = (sa.x * INV_K2) * gr.x + sb.x * INV_K2;
        o.y = (sa.y * INV_K2) * gr.y + sb.y * INV_K2;
        o.z = (sa.z * INV_K2) * gr.z + sb.z * INV_K2;
        o.w = (sa.w * INV_K2) * gr.w + sb.w * INV_K2;
        po[(size_t)row * W4 + t] = o;

        if (hl) {
            sa.x += la.x; sa.y += la.y; sa.z += la.z; sa.w += la.w;
            sb.x += lb.x; sb.y += lb.y; sb.z += lb.z; sb.w += lb.w;
        }
        if (ht) {
            sa.x -= ta.x; sa.y -= ta.y; sa.z -= ta.z; sa.w -= ta.w;
            sb.x -= tb.x; sb.y -= tb.y; sb.z -= tb.z; sb.w -= tb.w;
        }
    }
}

// ============================================================================
extern "C" void kernel_launch(void* const* d_in, const int* in_sizes, int n_in,
                              void* d_out, int out_size) {
    const float* guide = (const float*)d_in[0];
    const float* input = (const float*)d_in[1];
    float* out = (float*)d_out;

    k_h1<<<BATCH * HH / 4, 128>>>(guide, input);
    k_vh<<<dim3(HH / SEGV, BATCH), 256>>>();
    k_v2<<<dim3(1, HH / SEG, BATCH * 3), 128>>>(out);
}